// round 1
// baseline (speedup 1.0000x reference)
#include <cuda_runtime.h>
#include <cuda_bf16.h>

#define NPRED   25200
#define NCH     85
#define BATCH   16
#define TOPK    2048
#define CANDCAP 4096
#define MAXDET  300
#define CONF    0.25f
#define NMS_T   0.45f
#define NBIN    1024

// ---------------- scratch (no allocation allowed) ----------------
__device__ unsigned long long g_keys[BATCH * CANDCAP];
__device__ int                g_ncand[BATCH];
__device__ unsigned long long g_sorted[BATCH * TOPK];
__device__ float4             g_boxes[BATCH * TOPK];
__device__ float              g_scores[BATCH * TOPK];
__device__ int                g_labels[BATCH * TOPK];

// ---------------- K1: threshold + adaptive cutoff + compact ----------------
__global__ void k_select(const float* __restrict__ preds) {
    int img = blockIdx.x;
    __shared__ int hist[NBIN];
    __shared__ int s_cut, s_n;
    const float* base = preds + (size_t)img * NPRED * NCH;

    for (int b = threadIdx.x; b < NBIN; b += blockDim.x) hist[b] = 0;
    if (threadIdx.x == 0) s_n = 0;
    __syncthreads();

    for (int e = threadIdx.x; e < NPRED; e += blockDim.x) {
        float s = base[(size_t)e * NCH + 4];
        if (s > CONF) {
            int b = (int)((s - CONF) * (NBIN / 0.75f));
            b = b < 0 ? 0 : (b > NBIN - 1 ? NBIN - 1 : b);
            atomicAdd(&hist[b], 1);
        }
    }
    __syncthreads();

    if (threadIdx.x == 0) {
        int sum = 0, c = 0;
        for (int b = NBIN - 1; b >= 0; --b) {
            sum += hist[b];
            if (sum >= TOPK) { c = b; break; }
        }
        s_cut = c;
    }
    __syncthreads();
    int cut = s_cut;

    for (int e = threadIdx.x; e < NPRED; e += blockDim.x) {
        float s = base[(size_t)e * NCH + 4];
        if (s > CONF) {
            int b = (int)((s - CONF) * (NBIN / 0.75f));
            b = b < 0 ? 0 : (b > NBIN - 1 ? NBIN - 1 : b);
            if (b >= cut) {
                int slot = atomicAdd(&s_n, 1);
                if (slot < CANDCAP) {
                    unsigned long long key =
                        ((unsigned long long)__float_as_uint(s) << 32) |
                        (unsigned)(0xFFFFFFFFu - (unsigned)e);
                    g_keys[img * CANDCAP + slot] = key;
                }
            }
        }
    }
    __syncthreads();
    if (threadIdx.x == 0) g_ncand[img] = s_n < CANDCAP ? s_n : CANDCAP;
}

// ---------------- K2: bitonic sort (descending) of 4096 keys ----------------
__global__ void k_sort() {
    int img = blockIdx.x;
    __shared__ unsigned long long sk[CANDCAP];
    int n = g_ncand[img];
    for (int i = threadIdx.x; i < CANDCAP; i += blockDim.x)
        sk[i] = (i < n) ? g_keys[img * CANDCAP + i] : 0ULL;
    __syncthreads();

    for (int k = 2; k <= CANDCAP; k <<= 1) {
        for (int j = k >> 1; j > 0; j >>= 1) {
            for (int i = threadIdx.x; i < CANDCAP; i += blockDim.x) {
                int ixj = i ^ j;
                if (ixj > i) {
                    unsigned long long a = sk[i], b = sk[ixj];
                    bool descBlock = ((i & k) == 0);
                    if (descBlock ? (a < b) : (a > b)) { sk[i] = b; sk[ixj] = a; }
                }
            }
            __syncthreads();
        }
    }
    for (int i = threadIdx.x; i < TOPK; i += blockDim.x)
        g_sorted[img * TOPK + i] = sk[i];
}

// ---------------- K3: per-entry argmax(80) + box decode (warp/entry) --------
__global__ void k_gather(const float* __restrict__ preds,
                         const int* __restrict__ image_sizes) {
    int img  = blockIdx.y;
    int t    = blockIdx.x * (blockDim.x >> 5) + (threadIdx.x >> 5);
    int lane = threadIdx.x & 31;
    if (t >= TOPK) return;

    int o = img * TOPK + t;
    unsigned long long key = g_sorted[o];
    float score  = __uint_as_float((unsigned)(key >> 32));
    unsigned idx = 0xFFFFFFFFu - (unsigned)(key & 0xFFFFFFFFull);

    if (score <= CONF) {
        if (lane == 0) {
            g_scores[o] = 0.f; g_labels[o] = 0;
            float4 z = {0.f, 0.f, 0.f, 0.f};
            g_boxes[o] = z;
        }
        return;
    }
    const float* row = preds + ((size_t)img * NPRED + idx) * NCH;

    // argmax over 80 classes, first-index tie-break (matches jnp.argmax)
    float bv = -1e30f; int bc = 0;
    for (int c = lane; c < 80; c += 32) {
        float v = row[5 + c];
        if (v > bv) { bv = v; bc = c; }
    }
    for (int off = 16; off; off >>= 1) {
        float ov = __shfl_down_sync(0xffffffff, bv, off);
        int   oc = __shfl_down_sync(0xffffffff, bc, off);
        if (ov > bv || (ov == bv && oc < bc)) { bv = ov; bc = oc; }
    }

    if (lane == 0) {
        float x = row[0], y = row[1], w = row[2], h = row[3];
        float H = (float)image_sizes[img * 2 + 0];
        float W = (float)image_sizes[img * 2 + 1];
        float rh = H / 640.0f;
        float rw = W / 640.0f;
        float xmin = x - w * 0.5f;
        float ymin = y - h * 0.5f;
        float xmax = xmin + w;
        float ymax = ymin + h;
        float4 b;
        b.x = fminf(fmaxf(xmin * rw, 0.f), W);
        b.y = fminf(fmaxf(ymin * rh, 0.f), H);
        b.z = fminf(fmaxf(xmax * rw, 0.f), W);
        b.w = fminf(fmaxf(ymax * rh, 0.f), H);
        g_boxes[o]  = b;
        g_scores[o] = score;
        g_labels[o] = bc + 1;
    }
}

// ---------------- K4: greedy NMS, early-exit at 300 accepted ----------------
__global__ void k_nms(float* __restrict__ out) {
    int img = blockIdx.x;
    int tid = threadIdx.x;
    __shared__ float4 sbox[TOPK];
    __shared__ float  sscore[TOPK];
    __shared__ float4 abox[MAXDET];
    __shared__ float  aarea[MAXDET];
    __shared__ int    s_nacc, s_flag;

    for (int i = tid; i < TOPK; i += blockDim.x) {
        sbox[i]   = g_boxes[img * TOPK + i];
        sscore[i] = g_scores[img * TOPK + i];
    }
    if (tid == 0) { s_nacc = 0; s_flag = 0; }
    __syncthreads();

    for (int i = 0; i < TOPK; i++) {
        int na = s_nacc;
        if (na >= MAXDET) break;
        float cs = sscore[i];
        if (cs <= CONF) continue;

        float4 cb = sbox[i];
        float carea = fmaxf(cb.z - cb.x, 0.f) * fmaxf(cb.w - cb.y, 0.f);

        int sup = 0;
        for (int k = tid; k < na; k += blockDim.x) {
            float4 ab = abox[k];
            float lx = fmaxf(ab.x, cb.x), ly = fmaxf(ab.y, cb.y);
            float rx = fminf(ab.z, cb.z), ry = fminf(ab.w, cb.w);
            float iw = fmaxf(rx - lx, 0.f), ih = fmaxf(ry - ly, 0.f);
            float inter = iw * ih;
            float uni = aarea[k] + carea - inter;
            if (inter / (uni + 1e-7f) > NMS_T) sup = 1;
        }
        if (sup) s_flag = 1;
        __syncthreads();
        if (tid == 0) {
            if (!s_flag) {
                int k = s_nacc;
                abox[k]  = cb;
                aarea[k] = carea;
                float* orow = out + ((size_t)img * MAXDET + k) * 6;
                orow[0] = cb.x; orow[1] = cb.y; orow[2] = cb.z; orow[3] = cb.w;
                orow[4] = cs;
                orow[5] = (float)g_labels[img * TOPK + i];
                s_nacc = k + 1;
            }
            s_flag = 0;
        }
        __syncthreads();
    }

    int na = s_nacc;
    for (int j = na * 6 + tid; j < MAXDET * 6; j += blockDim.x)
        out[(size_t)img * MAXDET * 6 + j] = 0.f;
}

// ---------------- launch ----------------
extern "C" void kernel_launch(void* const* d_in, const int* in_sizes, int n_in,
                              void* d_out, int out_size) {
    const float* preds = (const float*)d_in[0];
    const int*   isz   = (const int*)d_in[1];
    float*       out   = (float*)d_out;

    k_select<<<BATCH, 256>>>(preds);
    k_sort<<<BATCH, 1024>>>();
    k_gather<<<dim3(TOPK / 4, BATCH), 128>>>(preds, isz);
    k_nms<<<BATCH, 256>>>(out);
}

// round 3
// speedup vs baseline: 1.7920x; 1.7920x over previous
#include <cuda_runtime.h>
#include <cuda_bf16.h>

#define NPRED   25200
#define NCH     85
#define BATCH   16
#define TOPK    2048
#define CANDCAP 4096
#define MAXDET  300
#define CONF    0.25f
#define NMS_T   0.45f
#define NBIN    1024
#define NWORDS  32      // 2048 bits / 64
#define NTILE   32      // TOPK/64
#define NTRI    (NTILE * (NTILE + 1) / 2)   // 528 upper-triangle tiles

// ---------------- scratch (no allocation allowed) ----------------
__device__ unsigned long long g_keys[BATCH * CANDCAP];
__device__ int                g_ncand[BATCH];
__device__ unsigned long long g_sorted[BATCH * TOPK];
__device__ float4             g_boxes[BATCH * TOPK];
__device__ float              g_scores[BATCH * TOPK];
__device__ int                g_labels[BATCH * TOPK];
__device__ unsigned long long g_mask[BATCH * TOPK * NWORDS];   // 8 MB

// ---------------- K1: threshold + adaptive cutoff + compact ----------------
__global__ void k_select(const float* __restrict__ preds) {
    int img = blockIdx.x;
    __shared__ int hist[NBIN];
    __shared__ int s_cut, s_n;
    const float* base = preds + (size_t)img * NPRED * NCH;

    for (int b = threadIdx.x; b < NBIN; b += blockDim.x) hist[b] = 0;
    if (threadIdx.x == 0) s_n = 0;
    __syncthreads();

    for (int e = threadIdx.x; e < NPRED; e += blockDim.x) {
        float s = base[(size_t)e * NCH + 4];
        if (s > CONF) {
            int b = (int)((s - CONF) * (NBIN / 0.75f));
            b = b < 0 ? 0 : (b > NBIN - 1 ? NBIN - 1 : b);
            atomicAdd(&hist[b], 1);
        }
    }
    __syncthreads();

    if (threadIdx.x == 0) {
        int sum = 0, c = 0;
        for (int b = NBIN - 1; b >= 0; --b) {
            sum += hist[b];
            if (sum >= TOPK) { c = b; break; }
        }
        s_cut = c;
    }
    __syncthreads();
    int cut = s_cut;

    for (int e = threadIdx.x; e < NPRED; e += blockDim.x) {
        float s = base[(size_t)e * NCH + 4];
        if (s > CONF) {
            int b = (int)((s - CONF) * (NBIN / 0.75f));
            b = b < 0 ? 0 : (b > NBIN - 1 ? NBIN - 1 : b);
            if (b >= cut) {
                int slot = atomicAdd(&s_n, 1);
                if (slot < CANDCAP) {
                    unsigned long long key =
                        ((unsigned long long)__float_as_uint(s) << 32) |
                        (unsigned)(0xFFFFFFFFu - (unsigned)e);
                    g_keys[img * CANDCAP + slot] = key;
                }
            }
        }
    }
    __syncthreads();
    if (threadIdx.x == 0) g_ncand[img] = s_n < CANDCAP ? s_n : CANDCAP;
}

// ---------------- K2: bitonic sort (descending) of 4096 keys ----------------
__global__ void k_sort() {
    int img = blockIdx.x;
    __shared__ unsigned long long sk[CANDCAP];
    int n = g_ncand[img];
    for (int i = threadIdx.x; i < CANDCAP; i += blockDim.x)
        sk[i] = (i < n) ? g_keys[img * CANDCAP + i] : 0ULL;
    __syncthreads();

    for (int k = 2; k <= CANDCAP; k <<= 1) {
        for (int j = k >> 1; j > 0; j >>= 1) {
            for (int i = threadIdx.x; i < CANDCAP; i += blockDim.x) {
                int ixj = i ^ j;
                if (ixj > i) {
                    unsigned long long a = sk[i], b = sk[ixj];
                    bool descBlock = ((i & k) == 0);
                    if (descBlock ? (a < b) : (a > b)) { sk[i] = b; sk[ixj] = a; }
                }
            }
            __syncthreads();
        }
    }
    for (int i = threadIdx.x; i < TOPK; i += blockDim.x)
        g_sorted[img * TOPK + i] = sk[i];
}

// ---------------- K3: per-entry argmax(80) + box decode (warp/entry) --------
__global__ void k_gather(const float* __restrict__ preds,
                         const int* __restrict__ image_sizes) {
    int img  = blockIdx.y;
    int t    = blockIdx.x * (blockDim.x >> 5) + (threadIdx.x >> 5);
    int lane = threadIdx.x & 31;
    if (t >= TOPK) return;

    int o = img * TOPK + t;
    unsigned long long key = g_sorted[o];
    float score  = __uint_as_float((unsigned)(key >> 32));
    unsigned idx = 0xFFFFFFFFu - (unsigned)(key & 0xFFFFFFFFull);

    if (score <= CONF) {
        if (lane == 0) {
            g_scores[o] = 0.f; g_labels[o] = 0;
            float4 z = {0.f, 0.f, 0.f, 0.f};
            g_boxes[o] = z;
        }
        return;
    }
    const float* row = preds + ((size_t)img * NPRED + idx) * NCH;

    // argmax over 80 classes, first-index tie-break (matches jnp.argmax)
    float bv = -1e30f; int bc = 0;
    for (int c = lane; c < 80; c += 32) {
        float v = row[5 + c];
        if (v > bv) { bv = v; bc = c; }
    }
    for (int off = 16; off; off >>= 1) {
        float ov = __shfl_down_sync(0xffffffff, bv, off);
        int   oc = __shfl_down_sync(0xffffffff, bc, off);
        if (ov > bv || (ov == bv && oc < bc)) { bv = ov; bc = oc; }
    }

    if (lane == 0) {
        float x = row[0], y = row[1], w = row[2], h = row[3];
        float H = (float)image_sizes[img * 2 + 0];
        float W = (float)image_sizes[img * 2 + 1];
        float rh = H / 640.0f;
        float rw = W / 640.0f;
        float xmin = x - w * 0.5f;
        float ymin = y - h * 0.5f;
        float xmax = xmin + w;
        float ymax = ymin + h;
        float4 b;
        b.x = fminf(fmaxf(xmin * rw, 0.f), W);
        b.y = fminf(fmaxf(ymin * rh, 0.f), H);
        b.z = fminf(fmaxf(xmax * rw, 0.f), W);
        b.w = fminf(fmaxf(ymax * rh, 0.f), H);
        g_boxes[o]  = b;
        g_scores[o] = score;
        g_labels[o] = bc + 1;
    }
}

// ---------------- K4: parallel pairwise IoU bitmask (upper triangle) --------
// blockIdx.x linearizes the 528 upper-triangle (rowBlk, colBlk) tile pairs.
// Each of 64 threads owns one row and computes one 64-bit column word.
__global__ void k_iou_mask() {
    int tri = blockIdx.x;
    // decode tri -> (rowBlk, colBlk) with colBlk >= rowBlk
    int rowBlk = 0;
    {
        int rem = tri;
        int span = NTILE;
        while (rem >= span) { rem -= span; span--; rowBlk++; }
        tri = rem;
    }
    int colBlk = rowBlk + tri;
    int img = blockIdx.y;

    __shared__ float4 cbox[64];
    __shared__ float  care[64];
    int tid  = threadIdx.x;
    int col0 = colBlk * 64;

    float4 cb = g_boxes[img * TOPK + col0 + tid];
    cbox[tid] = cb;
    care[tid] = fmaxf(cb.z - cb.x, 0.f) * fmaxf(cb.w - cb.y, 0.f);
    __syncthreads();

    int row = rowBlk * 64 + tid;
    float4 rb = g_boxes[img * TOPK + row];
    float  ra = fmaxf(rb.z - rb.x, 0.f) * fmaxf(rb.w - rb.y, 0.f);

    unsigned long long word = 0;
    #pragma unroll
    for (int c = 0; c < 64; c++) {
        int col = col0 + c;
        if (col > row) {
            float4 b2 = cbox[c];
            float lx = fmaxf(rb.x, b2.x), ly = fmaxf(rb.y, b2.y);
            float rx = fminf(rb.z, b2.z), ry = fminf(rb.w, b2.w);
            float iw = fmaxf(rx - lx, 0.f), ih = fmaxf(ry - ly, 0.f);
            float inter = iw * ih;
            float uni = ra + care[c] - inter;
            if (inter / (uni + 1e-7f) > NMS_T) word |= (1ull << c);
        }
    }
    g_mask[((size_t)img * TOPK + row) * NWORDS + colBlk] = word;
}

// ---------------- K5: warp-per-image greedy resolve (no barriers) -----------
__global__ void k_resolve(float* __restrict__ out) {
    int img  = blockIdx.x;
    int lane = threadIdx.x;   // 32 threads; lane owns bits [lane*64, lane*64+64)

    // alive bitmap: score > CONF
    unsigned long long S = 0;
    for (int b = 0; b < 64; b++) {
        float s = g_scores[img * TOPK + lane * 64 + b];
        if (s > CONF) S |= (1ull << b);
    }

    int nacc = 0;
    while (nacc < MAXDET) {
        unsigned act = __ballot_sync(0xffffffff, S != 0ull);
        if (!act) break;
        int fl = __ffs(act) - 1;
        unsigned long long Sf = __shfl_sync(0xffffffff, S, fl);
        int bit = __ffsll((long long)Sf) - 1;
        int i = fl * 64 + bit;

        unsigned long long m =
            g_mask[((size_t)img * TOPK + i) * NWORDS + lane];
        if (lane == fl) S &= ~(1ull << bit);
        S &= ~m;

        if (lane == 0) {
            float4 b = g_boxes[img * TOPK + i];
            float* orow = out + ((size_t)img * MAXDET + nacc) * 6;
            orow[0] = b.x; orow[1] = b.y; orow[2] = b.z; orow[3] = b.w;
            orow[4] = g_scores[img * TOPK + i];
            orow[5] = (float)g_labels[img * TOPK + i];
        }
        nacc++;
    }

    for (int j = nacc * 6 + lane; j < MAXDET * 6; j += 32)
        out[(size_t)img * MAXDET * 6 + j] = 0.f;
}

// ---------------- launch ----------------
extern "C" void kernel_launch(void* const* d_in, const int* in_sizes, int n_in,
                              void* d_out, int out_size) {
    const float* preds = (const float*)d_in[0];
    const int*   isz   = (const int*)d_in[1];
    float*       out   = (float*)d_out;

    k_select<<<BATCH, 256>>>(preds);
    k_sort<<<BATCH, 1024>>>();
    k_gather<<<dim3(TOPK / 4, BATCH), 128>>>(preds, isz);
    k_iou_mask<<<dim3(NTRI, BATCH), 64>>>();
    k_resolve<<<BATCH, 32>>>(out);
}